// round 5
// baseline (speedup 1.0000x reference)
#include <cuda_runtime.h>
#include <math.h>

// Problem constants
#define NTOK (8*8192)        // 65536 tokens
#define DIMC 512
#define NSLOT 64
#define CHUNKT 64
#define NCHUNK (NTOK/CHUNKT) // 1024

// ---------------- scratch (device globals; no allocation allowed) ----------------
__device__ float    g_v   [(size_t)NTOK*DIMC];
__device__ float    g_ret [(size_t)NTOK*DIMC];
__device__ float    g_ww  [(size_t)NTOK*NSLOT];
__device__ float    g_rw  [(size_t)NTOK*NSLOT];
__device__ unsigned g_Wv32[DIMC*DIMC];   // tf32 bits of Wv
__device__ unsigned g_Wo32[DIMC*DIMC];   // tf32 bits of (ln_g ⊙ Wo)
__device__ unsigned g_P32 [DIMC*128];    // tf32 bits of [Wk@SKᵀ | Wq@SKᵀ]
__device__ float    g_c   [128];         // [bk@SKᵀ | bq@SKᵀ]
__device__ float    g_b2  [DIMC];        // bo + ln_b @ Wo
__device__ float    g_mu  [NTOK];
__device__ float    g_ri  [NTOK];

// ---------------- TF32 helpers ----------------
__device__ __forceinline__ unsigned f2tf32(float x) {
    unsigned r;
    asm("cvt.rna.tf32.f32 %0, %1;" : "=r"(r) : "f"(x));
    return r;
}

__device__ __forceinline__ void mma_tf32(float c[4],
    unsigned a0, unsigned a1, unsigned a2, unsigned a3,
    unsigned b0, unsigned b1)
{
    asm volatile(
        "mma.sync.aligned.m16n8k8.row.col.f32.tf32.tf32.f32 "
        "{%0,%1,%2,%3},{%4,%5,%6,%7},{%8,%9},{%0,%1,%2,%3};"
        : "+f"(c[0]), "+f"(c[1]), "+f"(c[2]), "+f"(c[3])
        : "r"(a0), "r"(a1), "r"(a2), "r"(a3), "r"(b0), "r"(b1));
}

// -------- prep: slot projections, weight tf32 conversion, LN folding --------
// blocks 0..511:  P32[blk][s] = tf32(W{k,q}[blk] . SK[s]);  Wv32/Wo32 row blk
// block 512:      c[s] = b{k,q} . SK[s]
// block 513:      b2[n] = bo[n] + sum_k ln_b[k]*Wo[k][n]
__global__ __launch_bounds__(128) void prep_kernel(
    const float* __restrict__ Wk, const float* __restrict__ bk,
    const float* __restrict__ Wq, const float* __restrict__ bq,
    const float* __restrict__ SK,
    const float* __restrict__ Wv, const float* __restrict__ Wo,
    const float* __restrict__ lng, const float* __restrict__ lnb,
    const float* __restrict__ bo,
    unsigned* __restrict__ P32, float* __restrict__ c,
    unsigned* __restrict__ Wv32, unsigned* __restrict__ Wo32,
    float* __restrict__ b2)
{
    __shared__ float rk[DIMC];
    __shared__ float rq[DIMC];
    const int blk = blockIdx.x;
    const int s = threadIdx.x;          // 0..127

    if (blk == 513) {
        #pragma unroll
        for (int j = 0; j < 4; j++) {
            int n = s * 4 + j;
            float a = 0.f;
            for (int k = 0; k < DIMC; k++)
                a = fmaf(lnb[k], Wo[(size_t)k*DIMC + n], a);
            b2[n] = a + bo[n];
        }
        return;
    }

    const int slot = s & 63;
    if (blk < DIMC) {
        for (int d = s; d < DIMC; d += 128) {
            rk[d] = Wk[(size_t)blk*DIMC + d];
            rq[d] = Wq[(size_t)blk*DIMC + d];
        }
    } else {
        for (int d = s; d < DIMC; d += 128) { rk[d] = bk[d]; rq[d] = bq[d]; }
    }
    __syncthreads();
    const float* row = (s < 64) ? rk : rq;
    float a = 0.f;
    const float* skr = SK + (size_t)slot*DIMC;
    #pragma unroll 8
    for (int d = 0; d < DIMC; d++) a = fmaf(row[d], skr[d], a);

    if (blk < DIMC) {
        P32[(size_t)blk*128 + s] = f2tf32(a);
        const float gk = lng[blk];
        for (int n = s; n < DIMC; n += 128) {
            Wv32[(size_t)blk*DIMC + n] = f2tf32(Wv[(size_t)blk*DIMC + n]);
            Wo32[(size_t)blk*DIMC + n] = f2tf32(gk * Wo[(size_t)blk*DIMC + n]);
        }
    } else {
        c[s] = a;
    }
}

// ---------------- TF32 tensor-core GEMM (reg-staged double buffer) ----------------
// grid (nx, M/128). blocks x < nNormal: C[:, x*128..] = A'@B32 + bias (+resid)
//   where A' = (A - mu_row) * ri_row if row stats given, else A.
// block x == nNormal (if P32): logits = (A@P32 + c)*scale -> per-64-half softmax -> ww, rw.
#define TBM 128
#define TBN 128
#define TBK 32
#define ASRD 36
#define BSRD 136

__global__ __launch_bounds__(256) void gemm_tc(
    const float* __restrict__ A, const unsigned* __restrict__ B32,
    const float* __restrict__ bias, const float* __restrict__ resid,
    float* __restrict__ C,
    const float* __restrict__ rowmu, const float* __restrict__ rowri,
    const unsigned* __restrict__ P32, const float* __restrict__ cvec,
    const float* __restrict__ scale_p,
    float* __restrict__ ww, float* __restrict__ rw,
    int K, int nNormal)
{
    __shared__ __align__(16) unsigned sbuf[TBM*ASRD + TBK*BSRD]; // 35840 B
    unsigned (*As)[ASRD] = (unsigned (*)[ASRD])sbuf;
    unsigned (*Bs)[BSRD] = (unsigned (*)[BSRD])(sbuf + TBM*ASRD);
    float* L = (float*)sbuf;   // logits alias [128][68] (8704 floats <= 8960)
    __shared__ float csh[128];

    const int tid  = threadIdx.x;
    const int lane = tid & 31;
    const int wid  = tid >> 5;
    const int warp_m = wid >> 2;   // 0..1
    const int warp_n = wid & 3;    // 0..3
    const int gid = lane >> 2;
    const int tig = lane & 3;
    const int m0 = blockIdx.y * TBM;
    const bool is_logit = (P32 != nullptr) && ((int)blockIdx.x == nNormal);
    const int n0 = is_logit ? 0 : blockIdx.x * TBN;
    const unsigned* Bsrc = is_logit ? P32 : B32;
    const int ldB = is_logit ? 128 : DIMC;

    const int a_row = tid >> 1;
    const int a_colb = (tid & 1) * 16;
    const int b_row = tid >> 3;
    const int b_colb = (tid & 7) * 16;

    if (is_logit && tid < 128) csh[tid] = cvec[tid];

    // per-row LN affine (applied to A on staging)
    float r_mu = 0.f, r_ri = 1.f;
    if (rowmu) { r_mu = rowmu[m0 + a_row]; r_ri = rowri[m0 + a_row]; }

    const float* agb = A + (size_t)(m0 + a_row) * K + a_colb;
    const unsigned* bgb = Bsrc + (size_t)b_row * ldB + n0 + b_colb;

    float acc[4][4][4] = {};
    float4 pa[4];
    uint4  pb[4];

    #pragma unroll
    for (int v = 0; v < 4; v++) pa[v] = *(const float4*)(agb + v * 4);
    #pragma unroll
    for (int v = 0; v < 4; v++) pb[v] = *(const uint4*)(bgb + v * 4);

    for (int k0 = 0; k0 < K; k0 += TBK) {
        #pragma unroll
        for (int v = 0; v < 4; v++) {
            uint4 u;
            u.x = f2tf32((pa[v].x - r_mu) * r_ri);
            u.y = f2tf32((pa[v].y - r_mu) * r_ri);
            u.z = f2tf32((pa[v].z - r_mu) * r_ri);
            u.w = f2tf32((pa[v].w - r_mu) * r_ri);
            *(uint4*)&As[a_row][a_colb + v * 4] = u;
        }
        #pragma unroll
        for (int v = 0; v < 4; v++)
            *(uint4*)&Bs[b_row][b_colb + v * 4] = pb[v];
        __syncthreads();

        if (k0 + TBK < K) {
            const float* ag = agb + k0 + TBK;
            const unsigned* bg = bgb + (size_t)(k0 + TBK) * ldB;
            #pragma unroll
            for (int v = 0; v < 4; v++) pa[v] = *(const float4*)(ag + v * 4);
            #pragma unroll
            for (int v = 0; v < 4; v++) pb[v] = *(const uint4*)(bg + v * 4);
        }

        #pragma unroll
        for (int kk = 0; kk < TBK; kk += 8) {
            unsigned af[4][4];
            #pragma unroll
            for (int mt = 0; mt < 4; mt++) {
                int r = warp_m * 64 + mt * 16 + gid;
                af[mt][0] = As[r    ][kk + tig    ];
                af[mt][1] = As[r + 8][kk + tig    ];
                af[mt][2] = As[r    ][kk + tig + 4];
                af[mt][3] = As[r + 8][kk + tig + 4];
            }
            unsigned bf[4][2];
            #pragma unroll
            for (int nt = 0; nt < 4; nt++) {
                int cc = warp_n * 32 + nt * 8 + gid;
                bf[nt][0] = Bs[kk + tig    ][cc];
                bf[nt][1] = Bs[kk + tig + 4][cc];
            }
            #pragma unroll
            for (int mt = 0; mt < 4; mt++)
                #pragma unroll
                for (int nt = 0; nt < 4; nt++)
                    mma_tf32(acc[mt][nt], af[mt][0], af[mt][1], af[mt][2], af[mt][3],
                             bf[nt][0], bf[nt][1]);
        }
        __syncthreads();
    }

    if (!is_logit) {
        #pragma unroll
        for (int nt = 0; nt < 4; nt++) {
            int cb = n0 + warp_n * 32 + nt * 8 + 2 * tig;
            float b0 = bias[cb], b1 = bias[cb + 1];
            #pragma unroll
            for (int mt = 0; mt < 4; mt++) {
                int r0 = m0 + warp_m * 64 + mt * 16 + gid;
                int r1 = r0 + 8;
                size_t off0 = (size_t)r0 * DIMC + cb;
                size_t off1 = (size_t)r1 * DIMC + cb;
                float2 o0, o1;
                o0.x = acc[mt][nt][0] + b0; o0.y = acc[mt][nt][1] + b1;
                o1.x = acc[mt][nt][2] + b0; o1.y = acc[mt][nt][3] + b1;
                if (resid) {
                    float2 e0 = *(const float2*)(resid + off0);
                    float2 e1 = *(const float2*)(resid + off1);
                    o0.x += e0.x; o0.y += e0.y;
                    o1.x += e1.x; o1.y += e1.y;
                }
                *(float2*)(C + off0) = o0;
                *(float2*)(C + off1) = o1;
            }
        }
    } else {
        // two passes: pass0 -> ww (cols 0..63 = warp_n 0,1), pass1 -> rw (cols 64..127)
        const float sc = scale_p[0];
        #pragma unroll
        for (int pass = 0; pass < 2; pass++) {
            if ((warp_n >> 1) == pass) {
                int halfn = warp_n & 1;   // 0/1 -> 32-col slab within the 64-half
                #pragma unroll
                for (int nt = 0; nt < 4; nt++) {
                    int cl = halfn * 32 + nt * 8 + 2 * tig;   // 0..63 local
                    int cg = pass * 64 + cl;                  // global col
                    float c0v = csh[cg], c1v = csh[cg + 1];
                    #pragma unroll
                    for (int mt = 0; mt < 4; mt++) {
                        int r0 = warp_m * 64 + mt * 16 + gid;
                        L[ r0    *68 + cl    ] = (acc[mt][nt][0] + c0v) * sc;
                        L[ r0    *68 + cl + 1] = (acc[mt][nt][1] + c1v) * sc;
                        L[(r0+8) *68 + cl    ] = (acc[mt][nt][2] + c0v) * sc;
                        L[(r0+8) *68 + cl + 1] = (acc[mt][nt][3] + c1v) * sc;
                    }
                }
            }
            __syncthreads();
            {
                int t = tid >> 1, h = tid & 1;
                float* Lr = L + t*68 + h*32;
                float mx = -1e30f;
                #pragma unroll 8
                for (int s = 0; s < 32; s++) mx = fmaxf(mx, Lr[s]);
                mx = fmaxf(mx, __shfl_xor_sync(0xffffffffu, mx, 1));
                float sum = 0.f;
                #pragma unroll 8
                for (int s = 0; s < 32; s++) { float e = expf(Lr[s]-mx); Lr[s] = e; sum += e; }
                sum += __shfl_xor_sync(0xffffffffu, sum, 1);
                float rv = 1.f / sum;
                float* op = (pass ? rw : ww) + (size_t)(m0 + t) * NSLOT + h*32;
                #pragma unroll
                for (int s = 0; s < 32; s += 4) {
                    float4 w;
                    w.x = Lr[s]*rv; w.y = Lr[s+1]*rv; w.z = Lr[s+2]*rv; w.w = Lr[s+3]*rv;
                    *(float4*)(op + s) = w;
                }
            }
            __syncthreads();
        }
    }
}

// -------- per-chunk MMA: A = rw @ wwᵀ (causal), retrieved = A @ v --------
#define CSMEM (64*68*4*2 + 64*132*4)   // 68608

__global__ __launch_bounds__(256) void chunk_attn_mma(
    const float* __restrict__ rw, const float* __restrict__ ww,
    const float* __restrict__ v, float* __restrict__ ret)
{
    extern __shared__ __align__(16) char cb[];
    unsigned* RW = (unsigned*)cb;            // [64][68], later Amat
    unsigned* WT = RW + 64*68;               // [64][68]  (WT[s][u] = ww[u][s])
    unsigned* VS = WT + 64*68;               // [64][132]
    const int tid  = threadIdx.x;
    const int lane = tid & 31;
    const int wid  = tid >> 5;
    const int gid = lane >> 2;
    const int tig = lane & 3;
    const int chunk0 = blockIdx.x * CHUNKT;

    #pragma unroll
    for (int k = 0; k < 4; k++) {
        int idx = tid + k*256;
        int r = idx >> 4, c4 = (idx & 15) << 2;
        float4 a = *(const float4*)(rw + (size_t)(chunk0+r)*NSLOT + c4);
        RW[r*68 + c4    ] = f2tf32(a.x);
        RW[r*68 + c4 + 1] = f2tf32(a.y);
        RW[r*68 + c4 + 2] = f2tf32(a.z);
        RW[r*68 + c4 + 3] = f2tf32(a.w);
        float4 b = *(const float4*)(ww + (size_t)(chunk0+r)*NSLOT + c4);
        WT[(c4    )*68 + r] = f2tf32(b.x);
        WT[(c4 + 1)*68 + r] = f2tf32(b.y);
        WT[(c4 + 2)*68 + r] = f2tf32(b.z);
        WT[(c4 + 3)*68 + r] = f2tf32(b.w);
    }
    __syncthreads();

    const int wm = wid >> 2;
    const int wn = wid & 3;
    float a1[2][2][4] = {};
    #pragma unroll
    for (int kk = 0; kk < 64; kk += 8) {
        unsigned af[2][4];
        #pragma unroll
        for (int mt = 0; mt < 2; mt++) {
            int r = wm*32 + mt*16 + gid;
            af[mt][0] = RW[ r     *68 + kk + tig    ];
            af[mt][1] = RW[(r + 8)*68 + kk + tig    ];
            af[mt][2] = RW[ r     *68 + kk + tig + 4];
            af[mt][3] = RW[(r + 8)*68 + kk + tig + 4];
        }
        unsigned bf[2][2];
        #pragma unroll
        for (int nt = 0; nt < 2; nt++) {
            int cc = wn*16 + nt*8 + gid;
            bf[nt][0] = WT[(kk + tig    )*68 + cc];
            bf[nt][1] = WT[(kk + tig + 4)*68 + cc];
        }
        #pragma unroll
        for (int mt = 0; mt < 2; mt++)
            #pragma unroll
            for (int nt = 0; nt < 2; nt++)
                mma_tf32(a1[mt][nt], af[mt][0], af[mt][1], af[mt][2], af[mt][3],
                         bf[nt][0], bf[nt][1]);
    }
    __syncthreads();

    #pragma unroll
    for (int mt = 0; mt < 2; mt++) {
        int r0 = wm*32 + mt*16 + gid;
        #pragma unroll
        for (int nt = 0; nt < 2; nt++) {
            int cc = wn*16 + nt*8 + 2*tig;
            RW[ r0    *68 + cc    ] = f2tf32((cc     <= r0    ) ? a1[mt][nt][0] : 0.f);
            RW[ r0    *68 + cc + 1] = f2tf32((cc + 1 <= r0    ) ? a1[mt][nt][1] : 0.f);
            RW[(r0+8) *68 + cc    ] = f2tf32((cc     <= r0 + 8) ? a1[mt][nt][2] : 0.f);
            RW[(r0+8) *68 + cc + 1] = f2tf32((cc + 1 <= r0 + 8) ? a1[mt][nt][3] : 0.f);
        }
    }
    __syncthreads();

    unsigned afA[8][2][4];
    #pragma unroll
    for (int ks = 0; ks < 8; ks++) {
        #pragma unroll
        for (int mt = 0; mt < 2; mt++) {
            int r = wm*32 + mt*16 + gid;
            afA[ks][mt][0] = RW[ r     *68 + ks*8 + tig    ];
            afA[ks][mt][1] = RW[(r + 8)*68 + ks*8 + tig    ];
            afA[ks][mt][2] = RW[ r     *68 + ks*8 + tig + 4];
            afA[ks][mt][3] = RW[(r + 8)*68 + ks*8 + tig + 4];
        }
    }

    for (int d0 = 0; d0 < DIMC; d0 += 128) {
        #pragma unroll
        for (int k = 0; k < 8; k++) {
            int idx = tid + k*256;
            int r = idx >> 5, c4 = (idx & 31) << 2;
            float4 a = *(const float4*)(v + (size_t)(chunk0+r)*DIMC + d0 + c4);
            VS[r*132 + c4    ] = f2tf32(a.x);
            VS[r*132 + c4 + 1] = f2tf32(a.y);
            VS[r*132 + c4 + 2] = f2tf32(a.z);
            VS[r*132 + c4 + 3] = f2tf32(a.w);
        }
        __syncthreads();

        float a2[2][4][4] = {};
        #pragma unroll
        for (int ks = 0; ks < 8; ks++) {
            unsigned bf[4][2];
            #pragma unroll
            for (int nt = 0; nt < 4; nt++) {
                int cc = wn*32 + nt*8 + gid;
                bf[nt][0] = VS[(ks*8 + tig    )*132 + cc];
                bf[nt][1] = VS[(ks*8 + tig + 4)*132 + cc];
            }
            #pragma unroll
            for (int mt = 0; mt < 2; mt++)
                #pragma unroll
                for (int nt = 0; nt < 4; nt++)
                    mma_tf32(a2[mt][nt], afA[ks][mt][0], afA[ks][mt][1],
                             afA[ks][mt][2], afA[ks][mt][3], bf[nt][0], bf[nt][1]);
        }

        #pragma unroll
        for (int mt = 0; mt < 2; mt++) {
            int r0 = wm*32 + mt*16 + gid;
            #pragma unroll
            for (int nt = 0; nt < 4; nt++) {
                int cc = wn*32 + nt*8 + 2*tig;
                float2 o0, o1;
                o0.x = a2[mt][nt][0]; o0.y = a2[mt][nt][1];
                o1.x = a2[mt][nt][2]; o1.y = a2[mt][nt][3];
                *(float2*)(ret + (size_t)(chunk0 + r0    )*DIMC + d0 + cc) = o0;
                *(float2*)(ret + (size_t)(chunk0 + r0 + 8)*DIMC + d0 + cc) = o1;
            }
        }
        __syncthreads();
    }
}

// -------- LN row stats: mu, rinv --------
__global__ __launch_bounds__(256) void ln_stats(
    const float* __restrict__ X, float* __restrict__ mu, float* __restrict__ ri)
{
    const int row = blockIdx.x * 8 + (threadIdx.x >> 5);
    const int lane = threadIdx.x & 31;
    const float* xr = X + (size_t)row * DIMC;
    float s = 0.f, ss = 0.f;
    #pragma unroll
    for (int i = 0; i < 4; i++) {
        float4 v = *(const float4*)(xr + lane*4 + i*128);
        s  += v.x + v.y + v.z + v.w;
        ss += fmaf(v.x,v.x, fmaf(v.y,v.y, fmaf(v.z,v.z, v.w*v.w)));
    }
    #pragma unroll
    for (int o = 16; o > 0; o >>= 1) {
        s  += __shfl_xor_sync(0xffffffffu, s,  o);
        ss += __shfl_xor_sync(0xffffffffu, ss, o);
    }
    if (lane == 0) {
        float m = s * (1.f/512.f);
        mu[row] = m;
        ri[row] = rsqrtf(ss * (1.f/512.f) - m*m + 1e-5f);
    }
}

// ---------------- launch ----------------
extern "C" void kernel_launch(void* const* d_in, const int* in_sizes, int n_in,
                              void* d_out, int out_size)
{
    (void)in_sizes; (void)n_in; (void)out_size;
    const float* x   = (const float*)d_in[0];
    const float* sk  = (const float*)d_in[1];
    const float* Wk  = (const float*)d_in[2];
    const float* bk  = (const float*)d_in[3];
    const float* Wq  = (const float*)d_in[4];
    const float* bq  = (const float*)d_in[5];
    const float* Wv  = (const float*)d_in[6];
    const float* bv  = (const float*)d_in[7];
    const float* sc  = (const float*)d_in[8];
    const float* lng = (const float*)d_in[9];
    const float* lnb = (const float*)d_in[10];
    const float* Wo  = (const float*)d_in[11];
    const float* bo  = (const float*)d_in[12];
    float* out = (float*)d_out;

    float *vp,*retp,*wwp,*rwp,*cp,*b2p,*mup,*rip;
    unsigned *Wv32p,*Wo32p,*P32p;
    cudaGetSymbolAddress((void**)&vp,   g_v);
    cudaGetSymbolAddress((void**)&retp, g_ret);
    cudaGetSymbolAddress((void**)&wwp,  g_ww);
    cudaGetSymbolAddress((void**)&rwp,  g_rw);
    cudaGetSymbolAddress((void**)&cp,   g_c);
    cudaGetSymbolAddress((void**)&b2p,  g_b2);
    cudaGetSymbolAddress((void**)&mup,  g_mu);
    cudaGetSymbolAddress((void**)&rip,  g_ri);
    cudaGetSymbolAddress((void**)&Wv32p,g_Wv32);
    cudaGetSymbolAddress((void**)&Wo32p,g_Wo32);
    cudaGetSymbolAddress((void**)&P32p, g_P32);

    cudaFuncSetAttribute(chunk_attn_mma, cudaFuncAttributeMaxDynamicSharedMemorySize, CSMEM);

    prep_kernel<<<DIMC + 2, 128>>>(Wk, bk, Wq, bq, sk, Wv, Wo, lng, lnb, bo,
                                   P32p, cp, Wv32p, Wo32p, b2p);

    // V projection + fused logits/softmax (block x==4)
    dim3 gv(5, NTOK/TBM);
    gemm_tc<<<gv, 256>>>(x, Wv32p, bv, nullptr, vp,
                         nullptr, nullptr,
                         P32p, cp, sc, wwp, rwp, DIMC, 4);

    chunk_attn_mma<<<NCHUNK, 256, CSMEM>>>(rwp, wwp, vp, retp);

    ln_stats<<<NTOK/8, 256>>>(retp, mup, rip);

    // output projection: ((ret-mu)*ri) @ (g∘Wo) + (bo + lnb@Wo) + x
    dim3 go(4, NTOK/TBM);
    gemm_tc<<<go, 256>>>(retp, Wo32p, b2p, x, out,
                         mup, rip,
                         nullptr, nullptr, nullptr, nullptr, nullptr, DIMC, 4);
}

// round 7
// speedup vs baseline: 1.5694x; 1.5694x over previous
#include <cuda_runtime.h>
#include <cuda_fp16.h>
#include <math.h>
#include <stdint.h>

// Problem constants
#define NTOK (8*8192)        // 65536 tokens
#define DIMC 512
#define NSLOT 64
#define CHUNKT 64
#define NCHUNK (NTOK/CHUNKT) // 1024

// ---------------- scratch (device globals; no allocation allowed) ----------------
__device__ __half g_x16  [(size_t)NTOK*DIMC];
__device__ __half g_v16  [(size_t)NTOK*DIMC];
__device__ __half g_ret16[(size_t)NTOK*DIMC];
__device__ float  g_ww [(size_t)NTOK*NSLOT];
__device__ float  g_rw [(size_t)NTOK*NSLOT];
__device__ __half g_WvT16[DIMC*DIMC];   // half(Wv) transposed: [n][k]
__device__ __half g_WoT16[DIMC*DIMC];   // half(ln_g ⊙ Wo) transposed: [n][k]
__device__ __half g_P16T [128*DIMC];    // half([Wk@SKᵀ | Wq@SKᵀ]) transposed: [s][k]
__device__ float  g_c   [128];          // [bk@SKᵀ | bq@SKᵀ]
__device__ float  g_b2  [DIMC];         // bo + ln_b @ Wo
__device__ float  g_cs  [DIMC];         // colsum of (ln_g ⊙ Wo)
__device__ float  g_mu  [NTOK];
__device__ float  g_ri  [NTOK];

// ---------------- helpers ----------------
__device__ __forceinline__ unsigned f2tf32(float x) {
    unsigned r;
    asm("cvt.rna.tf32.f32 %0, %1;" : "=r"(r) : "f"(x));
    return r;
}

__device__ __forceinline__ void mma_tf32(float c[4],
    unsigned a0, unsigned a1, unsigned a2, unsigned a3,
    unsigned b0, unsigned b1)
{
    asm volatile(
        "mma.sync.aligned.m16n8k8.row.col.f32.tf32.tf32.f32 "
        "{%0,%1,%2,%3},{%4,%5,%6,%7},{%8,%9},{%0,%1,%2,%3};"
        : "+f"(c[0]), "+f"(c[1]), "+f"(c[2]), "+f"(c[3])
        : "r"(a0), "r"(a1), "r"(a2), "r"(a3), "r"(b0), "r"(b1));
}

__device__ __forceinline__ void mma_f16(float c[4],
    unsigned a0, unsigned a1, unsigned a2, unsigned a3,
    unsigned b0, unsigned b1)
{
    asm volatile(
        "mma.sync.aligned.m16n8k16.row.col.f32.f16.f16.f32 "
        "{%0,%1,%2,%3},{%4,%5,%6,%7},{%8,%9},{%0,%1,%2,%3};"
        : "+f"(c[0]), "+f"(c[1]), "+f"(c[2]), "+f"(c[3])
        : "r"(a0), "r"(a1), "r"(a2), "r"(a3), "r"(b0), "r"(b1));
}

__device__ __forceinline__ void cp16(unsigned smem_addr, const void* g) {
    asm volatile("cp.async.ca.shared.global [%0], [%1], 16;\n"
                 :: "r"(smem_addr), "l"(g));
}
#define CP_COMMIT() asm volatile("cp.async.commit_group;\n" ::: "memory")
#define CP_WAIT0()  asm volatile("cp.async.wait_group 0;\n" ::: "memory")

// ======== x -> half ========
__global__ __launch_bounds__(256) void to_half_kernel(
    const float* __restrict__ X, __half* __restrict__ Y)
{
    size_t base = ((size_t)blockIdx.x * 256 + threadIdx.x) * 8;
    float4 a = *(const float4*)(X + base);
    float4 b = *(const float4*)(X + base + 4);
    __half2 h[4];
    h[0] = __floats2half2_rn(a.x, a.y);
    h[1] = __floats2half2_rn(a.z, a.w);
    h[2] = __floats2half2_rn(b.x, b.y);
    h[3] = __floats2half2_rn(b.z, b.w);
    *(uint4*)(Y + base) = *(uint4*)h;
}

// ======== prep: slot projections (transposed half), weights half-T, LN folds ========
__global__ __launch_bounds__(128) void prep_kernel(
    const float* __restrict__ Wk, const float* __restrict__ bk,
    const float* __restrict__ Wq, const float* __restrict__ bq,
    const float* __restrict__ SK,
    const float* __restrict__ Wv, const float* __restrict__ Wo,
    const float* __restrict__ lng, const float* __restrict__ lnb,
    const float* __restrict__ bo,
    __half* __restrict__ P16T, float* __restrict__ c,
    __half* __restrict__ WvT16, __half* __restrict__ WoT16,
    float* __restrict__ b2, float* __restrict__ cs)
{
    __shared__ float rk[DIMC];
    __shared__ float rq[DIMC];
    const int blk = blockIdx.x;
    const int s = threadIdx.x;          // 0..127

    if (blk == 513) {
        #pragma unroll
        for (int j = 0; j < 4; j++) {
            int n = s * 4 + j;
            float a = 0.f, g = 0.f;
            for (int k = 0; k < DIMC; k++) {
                float w = Wo[(size_t)k*DIMC + n];
                a = fmaf(lnb[k], w, a);
                g = fmaf(lng[k], w, g);
            }
            b2[n] = a + bo[n];
            cs[n] = g;
        }
        return;
    }

    const int slot = s & 63;
    if (blk < DIMC) {
        for (int d = s; d < DIMC; d += 128) {
            rk[d] = Wk[(size_t)blk*DIMC + d];
            rq[d] = Wq[(size_t)blk*DIMC + d];
        }
    } else {
        for (int d = s; d < DIMC; d += 128) { rk[d] = bk[d]; rq[d] = bq[d]; }
    }
    __syncthreads();
    const float* row = (s < 64) ? rk : rq;
    float a = 0.f;
    const float* skr = SK + (size_t)slot*DIMC;
    #pragma unroll 8
    for (int d = 0; d < DIMC; d++) a = fmaf(row[d], skr[d], a);

    if (blk < DIMC) {
        const int k = blk;
        P16T[(size_t)s*DIMC + k] = __float2half_rn(a);
        const float gk = lng[k];
        for (int n = s; n < DIMC; n += 128) {
            WvT16[(size_t)n*DIMC + k] = __float2half_rn(Wv[(size_t)k*DIMC + n]);
            WoT16[(size_t)n*DIMC + k] = __float2half_rn(gk * Wo[(size_t)k*DIMC + n]);
        }
    } else {
        c[s] = a;
    }
}

// ======== fp16 tensor GEMM (cp.async 2-stage) ========
// grid (nx, NTOK/128). blocks x < nNormal: C = A16 @ BT16ᵀ + epilogue.
//   epilogue: if rowmu:  out = ri*acc - ri*mu*cs[n] + bias[n] + resid (fp32 C)
//             else:      out = acc + bias[n]  (half C16)
// block x == nNormal (if P16T): logits -> per-64-half softmax -> ww, rw (fp32).
#define HRD 20              // b32 per smem row (16 kpairs + 4 pad)
#define HSTG 10240          // bytes per operand stage: 128*20*4
#define HSMEM 40960         // 2*(A+B) stages
#define NIT 16              // K/32

__global__ __launch_bounds__(256) void gemm_h(
    const __half* __restrict__ A16, const __half* __restrict__ BT16,
    const float* __restrict__ bias, const float* __restrict__ resid,
    float* __restrict__ C, __half* __restrict__ C16,
    const float* __restrict__ rowmu, const float* __restrict__ rowri,
    const float* __restrict__ cs,
    const __half* __restrict__ P16T, const float* __restrict__ cvec,
    const float* __restrict__ scale_p,
    float* __restrict__ ww, float* __restrict__ rw, int nNormal)
{
    extern __shared__ __align__(16) char smraw[];
    float* L = (float*)smraw;          // logits alias [128][68] = 34816B
    __shared__ float csh[128];

    const int tid  = threadIdx.x;
    const int lane = tid & 31;
    const int wid  = tid >> 5;
    const int warp_m = wid >> 2;   // 0..1
    const int warp_n = wid & 3;    // 0..3
    const int gid = lane >> 2;
    const int tig = lane & 3;
    const int m0 = blockIdx.y * 128;
    const bool is_logit = (P16T != nullptr) && ((int)blockIdx.x == nNormal);
    const int n0 = is_logit ? 0 : blockIdx.x * 128;
    const __half* Bsrc = is_logit ? P16T : BT16;

    if (is_logit && tid < 128) csh[tid] = cvec[tid];

    const unsigned sb = (unsigned)__cvta_generic_to_shared(smraw);

    // staging indices: 512 16B-chunks per operand tile, 2 per thread
    const int r0c = tid >> 1;                 // chunk set 0: rows 0..127
    const int j0c = (tid & 1) * 2;            // 16B unit 0..3 step — handled below
    (void)r0c; (void)j0c;

    float acc[4][4][4] = {};

    // each thread stages 2 chunks of A and 2 of B per stage:
    //   chunk id c in {tid, tid+256}; r = c>>2, j = c&3
    auto stageA = [&](int st, int k0) {
        #pragma unroll
        for (int h = 0; h < 2; h++) {
            int cch = tid + h*256;
            int r = cch >> 2, j = cch & 3;
            unsigned dst = sb + st*HSTG + (unsigned)((r*HRD + j*4)*4);
            cp16(dst, A16 + (size_t)(m0 + r)*DIMC + k0 + j*8);
        }
    };
    auto stageB = [&](int st, int k0) {
        #pragma unroll
        for (int h = 0; h < 2; h++) {
            int cch = tid + h*256;
            int r = cch >> 2, j = cch & 3;
            unsigned dst = sb + 2*HSTG + st*HSTG + (unsigned)((r*HRD + j*4)*4);
            cp16(dst, Bsrc + (size_t)(n0 + r)*DIMC + k0 + j*8);
        }
    };

    stageA(0, 0); stageB(0, 0); CP_COMMIT();

    for (int it = 0; it < NIT; it++) {
        CP_WAIT0();
        __syncthreads();
        if (it + 1 < NIT) {
            int st = (it + 1) & 1;
            stageA(st, (it + 1) * 32);
            stageB(st, (it + 1) * 32);
            CP_COMMIT();
        }
        const int st = it & 1;
        const unsigned* Ah = (const unsigned*)(smraw + st*HSTG);
        const unsigned* Bh = (const unsigned*)(smraw + 2*HSTG + st*HSTG);

        #pragma unroll
        for (int ks = 0; ks < 2; ks++) {
            const int kb = ks * 8;
            unsigned af[4][4];
            #pragma unroll
            for (int mt = 0; mt < 4; mt++) {
                int r = warp_m * 64 + mt * 16 + gid;
                af[mt][0] = Ah[ r     *HRD + kb + tig    ];
                af[mt][1] = Ah[(r + 8)*HRD + kb + tig    ];
                af[mt][2] = Ah[ r     *HRD + kb + tig + 4];
                af[mt][3] = Ah[(r + 8)*HRD + kb + tig + 4];
            }
            unsigned bf[4][2];
            #pragma unroll
            for (int nt = 0; nt < 4; nt++) {
                int cc = warp_n * 32 + nt * 8 + gid;
                bf[nt][0] = Bh[cc*HRD + kb + tig    ];
                bf[nt][1] = Bh[cc*HRD + kb + tig + 4];
            }
            #pragma unroll
            for (int mt = 0; mt < 4; mt++)
                #pragma unroll
                for (int nt = 0; nt < 4; nt++)
                    mma_f16(acc[mt][nt], af[mt][0], af[mt][1], af[mt][2], af[mt][3],
                            bf[nt][0], bf[nt][1]);
        }
        __syncthreads();
    }

    if (!is_logit) {
        #pragma unroll
        for (int nt = 0; nt < 4; nt++) {
            int cb = n0 + warp_n * 32 + nt * 8 + 2 * tig;
            float b0 = bias[cb], b1 = bias[cb + 1];
            float cs0 = 0.f, cs1 = 0.f;
            if (rowmu) { cs0 = cs[cb]; cs1 = cs[cb + 1]; }
            #pragma unroll
            for (int mt = 0; mt < 4; mt++) {
                int rA = m0 + warp_m * 64 + mt * 16 + gid;
                int rB = rA + 8;
                size_t offA = (size_t)rA * DIMC + cb;
                size_t offB = (size_t)rB * DIMC + cb;
                if (rowmu) {
                    float muA = rowmu[rA], riA = rowri[rA];
                    float muB = rowmu[rB], riB = rowri[rB];
                    float2 o0, o1;
                    o0.x = riA*acc[mt][nt][0] - riA*muA*cs0 + b0;
                    o0.y = riA*acc[mt][nt][1] - riA*muA*cs1 + b1;
                    o1.x = riB*acc[mt][nt][2] - riB*muB*cs0 + b0;
                    o1.y = riB*acc[mt][nt][3] - riB*muB*cs1 + b1;
                    float2 e0 = *(const float2*)(resid + offA);
                    float2 e1 = *(const float2*)(resid + offB);
                    o0.x += e0.x; o0.y += e0.y;
                    o1.x += e1.x; o1.y += e1.y;
                    *(float2*)(C + offA) = o0;
                    *(float2*)(C + offB) = o1;
                } else {
                    *(__half2*)(C16 + offA) =
                        __floats2half2_rn(acc[mt][nt][0] + b0, acc[mt][nt][1] + b1);
                    *(__half2*)(C16 + offB) =
                        __floats2half2_rn(acc[mt][nt][2] + b0, acc[mt][nt][3] + b1);
                }
            }
        }
    } else {
        const float sc = scale_p[0];
        #pragma unroll
        for (int pass = 0; pass < 2; pass++) {
            if ((warp_n >> 1) == pass) {
                int halfn = warp_n & 1;
                #pragma unroll
                for (int nt = 0; nt < 4; nt++) {
                    int cl = halfn * 32 + nt * 8 + 2 * tig;
                    int cg = pass * 64 + cl;
                    float c0v = csh[cg], c1v = csh[cg + 1];
                    #pragma unroll
                    for (int mt = 0; mt < 4; mt++) {
                        int rr = warp_m * 64 + mt * 16 + gid;
                        L[ rr    *68 + cl    ] = (acc[mt][nt][0] + c0v) * sc;
                        L[ rr    *68 + cl + 1] = (acc[mt][nt][1] + c1v) * sc;
                        L[(rr+8) *68 + cl    ] = (acc[mt][nt][2] + c0v) * sc;
                        L[(rr+8) *68 + cl + 1] = (acc[mt][nt][3] + c1v) * sc;
                    }
                }
            }
            __syncthreads();
            {
                int t = tid >> 1, hh = tid & 1;
                float* Lr = L + t*68 + hh*32;
                float mx = -1e30f;
                #pragma unroll 8
                for (int s = 0; s < 32; s++) mx = fmaxf(mx, Lr[s]);
                mx = fmaxf(mx, __shfl_xor_sync(0xffffffffu, mx, 1));
                float sum = 0.f;
                #pragma unroll 8
                for (int s = 0; s < 32; s++) { float e = expf(Lr[s]-mx); Lr[s] = e; sum += e; }
                sum += __shfl_xor_sync(0xffffffffu, sum, 1);
                float rv = 1.f / sum;
                float* op = (pass ? rw : ww) + (size_t)(m0 + t) * NSLOT + hh*32;
                #pragma unroll
                for (int s = 0; s < 32; s += 4) {
                    float4 w;
                    w.x = Lr[s]*rv; w.y = Lr[s+1]*rv; w.z = Lr[s+2]*rv; w.w = Lr[s+3]*rv;
                    *(float4*)(op + s) = w;
                }
            }
            __syncthreads();
        }
    }
}

// ======== per-chunk tf32 MMA: A = rw @ wwᵀ (causal), retrieved = A @ v16 ========
#define CSMEM (64*68*4*2 + 64*132*4)   // 68608

__global__ __launch_bounds__(256) void chunk_attn_mma(
    const float* __restrict__ rw, const float* __restrict__ ww,
    const __half* __restrict__ v16, __half* __restrict__ ret16)
{
    extern __shared__ __align__(16) char cbuf[];
    unsigned* RW = (unsigned*)cbuf;
    unsigned* WT = RW + 64*68;
    unsigned* VS = WT + 64*68;
    const int tid  = threadIdx.x;
    const int lane = tid & 31;
    const int wid  = tid >> 5;
    const int gid = lane >> 2;
    const int tig = lane & 3;
    const int chunk0 = blockIdx.x * CHUNKT;

    #pragma unroll
    for (int k = 0; k < 4; k++) {
        int idx = tid + k*256;
        int r = idx >> 4, c4 = (idx & 15) << 2;
        float4 a = *(const float4*)(rw + (size_t)(chunk0+r)*NSLOT + c4);
        RW[r*68 + c4    ] = f2tf32(a.x);
        RW[r*68 + c4 + 1] = f2tf32(a.y);
        RW[r*68 + c4 + 2] = f2tf32(a.z);
        RW[r*68 + c4 + 3] = f2tf32(a.w);
        float4 b = *(const float4*)(ww + (size_t)(chunk0+r)*NSLOT + c4);
        WT[(c4    )*68 + r] = f2tf32(b.x);
        WT[(c4 + 1)*68 + r] = f2tf32(b.y);
        WT[(c4 + 2)*68 + r] = f2tf32(b.z);
        WT[(c4 + 3)*68 + r] = f2tf32(b.w);
    }
    __syncthreads();

    const int wm = wid >> 2;
    const int wn = wid & 3;
    float a1[2][2][4] = {};
    #pragma unroll
    for (int kk = 0; kk < 64; kk += 8) {
        unsigned af[2][4];
        #pragma unroll
        for (int mt = 0; mt < 2; mt++) {
            int r = wm*32 + mt*16 + gid;
            af[mt][0] = RW[ r     *68 + kk + tig    ];
            af[mt][1] = RW[(r + 8)*68 + kk + tig    ];
            af[mt][2] = RW[ r     *68 + kk + tig + 4];
            af[mt][3] = RW[(r + 8)*68 + kk + tig + 4];
        }
        unsigned bf[2][2];
        #pragma unroll
        for (int nt = 0; nt < 2; nt++) {
            int cc = wn*16 + nt*8 + gid;
            bf[nt][0] = WT[(kk + tig    )*68 + cc];
            bf[nt][1] = WT[(kk + tig + 4)*68 + cc];
        }
        #pragma unroll
        for (int mt = 0; mt < 2; mt++)
            #pragma unroll
            for (int nt = 0; nt < 2; nt++)
                mma_tf32(a1[mt][nt], af[mt][0], af[mt][1], af[mt][2], af[mt][3],
                         bf[nt][0], bf[nt][1]);
    }
    __syncthreads();

    #pragma unroll
    for (int mt = 0; mt < 2; mt++) {
        int r0 = wm*32 + mt*16 + gid;
        #pragma unroll
        for (int nt = 0; nt < 2; nt++) {
            int cc = wn*16 + nt*8 + 2*tig;
            RW[ r0    *68 + cc    ] = f2tf32((cc     <= r0    ) ? a1[mt][nt][0] : 0.f);
            RW[ r0    *68 + cc + 1] = f2tf32((cc + 1 <= r0    ) ? a1[mt][nt][1] : 0.f);
            RW[(r0+8) *68 + cc    ] = f2tf32((cc     <= r0 + 8) ? a1[mt][nt][2] : 0.f);
            RW[(r0+8) *68 + cc + 1] = f2tf32((cc + 1 <= r0 + 8) ? a1[mt][nt][3] : 0.f);
        }
    }
    __syncthreads();

    unsigned afA[8][2][4];
    #pragma unroll
    for (int ks = 0; ks < 8; ks++) {
        #pragma unroll
        for (int mt = 0; mt < 2; mt++) {
            int r = wm*32 + mt*16 + gid;
            afA[ks][mt][0] = RW[ r     *68 + ks*8 + tig    ];
            afA[ks][mt][1] = RW[(r + 8)*68 + ks*8 + tig    ];
            afA[ks][mt][2] = RW[ r     *68 + ks*8 + tig + 4];
            afA[ks][mt][3] = RW[(r + 8)*68 + ks*8 + tig + 4];
        }
    }

    for (int d0 = 0; d0 < DIMC; d0 += 128) {
        #pragma unroll
        for (int k = 0; k < 8; k++) {
            int idx = tid + k*256;
            int r = idx >> 5, c4 = (idx & 31) << 2;
            uint2 hv = *(const uint2*)(v16 + (size_t)(chunk0+r)*DIMC + d0 + c4);
            float2 f0 = __half22float2(*(__half2*)&hv.x);
            float2 f1 = __half22float2(*(__half2*)&hv.y);
            VS[r*132 + c4    ] = f2tf32(f0.x);
            VS[r*132 + c4 + 1] = f2tf32(f0.y);
            VS[r*132 + c4 + 2] = f2tf32(f1.x);
            VS[r*132 + c4 + 3] = f2tf32(f1.y);
        }
        __syncthreads();

        float a2[2][4][4] = {};
        #pragma unroll
        for (int ks = 0; ks < 8; ks++) {
            unsigned bf[4][2];
            #pragma unroll
            for (int nt = 0; nt < 4; nt++) {
                int cc = wn*32 + nt*8 + gid;
                bf[nt][0] = VS[(ks*8 + tig    )*132 + cc];
                bf[nt][1] = VS[(ks*8 + tig + 4)*132 + cc];
            }
            #pragma unroll
            for (int mt = 0; mt < 2; mt++)
                #pragma unroll
                for (int nt = 0; nt < 4; nt++)
                    mma_tf32(a2[mt][nt], afA[ks][mt][0], afA[ks][mt][1],
                             afA[ks][mt][2], afA[ks][mt][3], bf[nt][0], bf[nt][1]);
        }

        #pragma unroll
        for (int mt = 0; mt < 2; mt++) {
            int r0 = wm*32 + mt*16 + gid;
            #pragma unroll
            for (int nt = 0; nt < 4; nt++) {
                int cc = wn*32 + nt*8 + 2*tig;
                *(__half2*)(ret16 + (size_t)(chunk0 + r0    )*DIMC + d0 + cc) =
                    __floats2half2_rn(a2[mt][nt][0], a2[mt][nt][1]);
                *(__half2*)(ret16 + (size_t)(chunk0 + r0 + 8)*DIMC + d0 + cc) =
                    __floats2half2_rn(a2[mt][nt][2], a2[mt][nt][3]);
            }
        }
        __syncthreads();
    }
}

// ======== LN row stats from half ========
__global__ __launch_bounds__(256) void ln_stats(
    const __half* __restrict__ X16, float* __restrict__ mu, float* __restrict__ ri)
{
    const int row = blockIdx.x * 8 + (threadIdx.x >> 5);
    const int lane = threadIdx.x & 31;
    const __half* xr = X16 + (size_t)row * DIMC;
    float s = 0.f, ss = 0.f;
    #pragma unroll
    for (int i = 0; i < 2; i++) {
        uint4 u = *(const uint4*)(xr + lane*8 + i*256);
        const unsigned* up = (const unsigned*)&u;
        #pragma unroll
        for (int j = 0; j < 4; j++) {
            float2 f = __half22float2(*(__half2*)&up[j]);
            s  += f.x + f.y;
            ss += fmaf(f.x, f.x, f.y*f.y);
        }
    }
    #pragma unroll
    for (int o = 16; o > 0; o >>= 1) {
        s  += __shfl_xor_sync(0xffffffffu, s,  o);
        ss += __shfl_xor_sync(0xffffffffu, ss, o);
    }
    if (lane == 0) {
        float m = s * (1.f/512.f);
        mu[row] = m;
        ri[row] = rsqrtf(ss * (1.f/512.f) - m*m + 1e-5f);
    }
}

// ---------------- launch ----------------
extern "C" void kernel_launch(void* const* d_in, const int* in_sizes, int n_in,
                              void* d_out, int out_size)
{
    (void)in_sizes; (void)n_in; (void)out_size;
    const float* x   = (const float*)d_in[0];
    const float* sk  = (const float*)d_in[1];
    const float* Wk  = (const float*)d_in[2];
    const float* bk  = (const float*)d_in[3];
    const float* Wq  = (const float*)d_in[4];
    const float* bq  = (const float*)d_in[5];
    const float* Wv  = (const float*)d_in[6];
    const float* bv  = (const float*)d_in[7];
    const float* sc  = (const float*)d_in[8];
    const float* lng = (const float*)d_in[9];
    const float* lnb = (const float*)d_in[10];
    const float* Wo  = (const float*)d_in[11];
    const float* bo  = (const float*)d_in[12];
    float* out = (float*)d_out;

    float *wwp,*rwp,*cp,*b2p,*csp,*mup,*rip;
    __half *x16p,*v16p,*ret16p,*WvTp,*WoTp,*P16p;
    cudaGetSymbolAddress((void**)&x16p,  g_x16);
    cudaGetSymbolAddress((void**)&v16p,  g_v16);
    cudaGetSymbolAddress((void**)&ret16p,g_ret16);
    cudaGetSymbolAddress((void**)&wwp,   g_ww);
    cudaGetSymbolAddress((void**)&rwp,   g_rw);
    cudaGetSymbolAddress((void**)&cp,    g_c);
    cudaGetSymbolAddress((void**)&b2p,   g_b2);
    cudaGetSymbolAddress((void**)&csp,   g_cs);
    cudaGetSymbolAddress((void**)&mup,   g_mu);
    cudaGetSymbolAddress((void**)&rip,   g_ri);
    cudaGetSymbolAddress((void**)&WvTp,  g_WvT16);
    cudaGetSymbolAddress((void**)&WoTp,  g_WoT16);
    cudaGetSymbolAddress((void**)&P16p,  g_P16T);

    cudaFuncSetAttribute(gemm_h, cudaFuncAttributeMaxDynamicSharedMemorySize, HSMEM);
    cudaFuncSetAttribute(chunk_attn_mma, cudaFuncAttributeMaxDynamicSharedMemorySize, CSMEM);

    prep_kernel<<<DIMC + 2, 128>>>(Wk, bk, Wq, bq, sk, Wv, Wo, lng, lnb, bo,
                                   P16p, cp, WvTp, WoTp, b2p, csp);

    to_half_kernel<<<((size_t)NTOK*DIMC/8)/256, 256>>>(x, x16p);

    // V = x16 @ Wv + bv (half out) ; block x==4: logits + softmax
    dim3 gv(5, NTOK/128);
    gemm_h<<<gv, 256, HSMEM>>>(x16p, WvTp, bv, nullptr, nullptr, v16p,
                               nullptr, nullptr, nullptr,
                               P16p, cp, sc, wwp, rwp, 4);

    chunk_attn_mma<<<NCHUNK, 256, CSMEM>>>(rwp, wwp, v16p, ret16p);

    ln_stats<<<NTOK/8, 256>>>(ret16p, mup, rip);

    // out = ri*(ret16 @ (g∘Wo)) - ri*mu*colsum + b2 + x  (fp32 out)
    dim3 go(4, NTOK/128);
    gemm_h<<<go, 256, HSMEM>>>(ret16p, WoTp, b2p, x, out, nullptr,
                               mup, rip, csp,
                               nullptr, nullptr, nullptr, nullptr, nullptr, 4);
}

// round 8
// speedup vs baseline: 1.6145x; 1.0287x over previous
#include <cuda_runtime.h>
#include <cuda_fp16.h>
#include <math.h>
#include <stdint.h>

// Problem constants
#define NTOK (8*8192)        // 65536 tokens
#define DIMC 512
#define NSLOT 64
#define CHUNKT 64
#define NCHUNK (NTOK/CHUNKT) // 1024

// ---------------- scratch ----------------
__device__ __half g_x16  [(size_t)NTOK*DIMC];
__device__ __half g_v16  [(size_t)NTOK*DIMC];
__device__ __half g_ret16[(size_t)NTOK*DIMC];
__device__ float  g_ww [(size_t)NTOK*NSLOT];
__device__ float  g_rw [(size_t)NTOK*NSLOT];
__device__ __half g_WvT16[DIMC*DIMC];   // half(Wv) transposed: [n][k]
__device__ __half g_WoT16[DIMC*DIMC];   // half(ln_g ⊙ Wo) transposed: [n][k]
__device__ __half g_P16T [128*DIMC];    // half([Wk@SKᵀ | Wq@SKᵀ]) transposed: [s][k]
__device__ float  g_c   [128];
__device__ float  g_b2  [DIMC];         // bo + ln_b @ Wo
__device__ float  g_cs  [DIMC];         // colsum of (ln_g ⊙ Wo)
__device__ float  g_mu  [NTOK];
__device__ float  g_ri  [NTOK];

// ---------------- helpers ----------------
__device__ __forceinline__ unsigned f2tf32(float x) {
    unsigned r;
    asm("cvt.rna.tf32.f32 %0, %1;" : "=r"(r) : "f"(x));
    return r;
}

__device__ __forceinline__ void mma_tf32(float c[4],
    unsigned a0, unsigned a1, unsigned a2, unsigned a3,
    unsigned b0, unsigned b1)
{
    asm volatile(
        "mma.sync.aligned.m16n8k8.row.col.f32.tf32.tf32.f32 "
        "{%0,%1,%2,%3},{%4,%5,%6,%7},{%8,%9},{%0,%1,%2,%3};"
        : "+f"(c[0]), "+f"(c[1]), "+f"(c[2]), "+f"(c[3])
        : "r"(a0), "r"(a1), "r"(a2), "r"(a3), "r"(b0), "r"(b1));
}

__device__ __forceinline__ void mma_f16(float c[4],
    unsigned a0, unsigned a1, unsigned a2, unsigned a3,
    unsigned b0, unsigned b1)
{
    asm volatile(
        "mma.sync.aligned.m16n8k16.row.col.f32.f16.f16.f32 "
        "{%0,%1,%2,%3},{%4,%5,%6,%7},{%8,%9},{%0,%1,%2,%3};"
        : "+f"(c[0]), "+f"(c[1]), "+f"(c[2]), "+f"(c[3])
        : "r"(a0), "r"(a1), "r"(a2), "r"(a3), "r"(b0), "r"(b1));
}

__device__ __forceinline__ void ldsm_x4(
    unsigned& r0, unsigned& r1, unsigned& r2, unsigned& r3, unsigned addr)
{
    asm volatile("ldmatrix.sync.aligned.m8n8.x4.shared.b16 {%0,%1,%2,%3}, [%4];"
        : "=r"(r0), "=r"(r1), "=r"(r2), "=r"(r3) : "r"(addr));
}

__device__ __forceinline__ void cpcg16(unsigned smem_addr, const void* g) {
    asm volatile("cp.async.cg.shared.global [%0], [%1], 16;\n"
                 :: "r"(smem_addr), "l"(g));
}
#define CP_COMMIT() asm volatile("cp.async.commit_group;\n" ::: "memory")
#define CP_WAIT0()  asm volatile("cp.async.wait_group 0;\n" ::: "memory")
#define CP_WAIT1()  asm volatile("cp.async.wait_group 1;\n" ::: "memory")

// ======== x -> half ========
__global__ __launch_bounds__(256) void to_half_kernel(
    const float* __restrict__ X, __half* __restrict__ Y)
{
    size_t base = ((size_t)blockIdx.x * 256 + threadIdx.x) * 8;
    float4 a = *(const float4*)(X + base);
    float4 b = *(const float4*)(X + base + 4);
    __half2 h[4];
    h[0] = __floats2half2_rn(a.x, a.y);
    h[1] = __floats2half2_rn(a.z, a.w);
    h[2] = __floats2half2_rn(b.x, b.y);
    h[3] = __floats2half2_rn(b.z, b.w);
    *(uint4*)(Y + base) = *(uint4*)h;
}

// ======== prep ========
__global__ __launch_bounds__(128) void prep_kernel(
    const float* __restrict__ Wk, const float* __restrict__ bk,
    const float* __restrict__ Wq, const float* __restrict__ bq,
    const float* __restrict__ SK,
    const float* __restrict__ Wv, const float* __restrict__ Wo,
    const float* __restrict__ lng, const float* __restrict__ lnb,
    const float* __restrict__ bo,
    __half* __restrict__ P16T, float* __restrict__ c,
    __half* __restrict__ WvT16, __half* __restrict__ WoT16,
    float* __restrict__ b2, float* __restrict__ cs)
{
    __shared__ float rk[DIMC];
    __shared__ float rq[DIMC];
    const int blk = blockIdx.x;
    const int s = threadIdx.x;

    if (blk == 513) {
        #pragma unroll
        for (int j = 0; j < 4; j++) {
            int n = s * 4 + j;
            float a = 0.f, g = 0.f;
            for (int k = 0; k < DIMC; k++) {
                float w = Wo[(size_t)k*DIMC + n];
                a = fmaf(lnb[k], w, a);
                g = fmaf(lng[k], w, g);
            }
            b2[n] = a + bo[n];
            cs[n] = g;
        }
        return;
    }

    const int slot = s & 63;
    if (blk < DIMC) {
        for (int d = s; d < DIMC; d += 128) {
            rk[d] = Wk[(size_t)blk*DIMC + d];
            rq[d] = Wq[(size_t)blk*DIMC + d];
        }
    } else {
        for (int d = s; d < DIMC; d += 128) { rk[d] = bk[d]; rq[d] = bq[d]; }
    }
    __syncthreads();
    const float* row = (s < 64) ? rk : rq;
    float a = 0.f;
    const float* skr = SK + (size_t)slot*DIMC;
    #pragma unroll 8
    for (int d = 0; d < DIMC; d++) a = fmaf(row[d], skr[d], a);

    if (blk < DIMC) {
        const int k = blk;
        P16T[(size_t)s*DIMC + k] = __float2half_rn(a);
        const float gk = lng[k];
        for (int n = s; n < DIMC; n += 128) {
            WvT16[(size_t)n*DIMC + k] = __float2half_rn(Wv[(size_t)k*DIMC + n]);
            WoT16[(size_t)n*DIMC + k] = __float2half_rn(gk * Wo[(size_t)k*DIMC + n]);
        }
    } else {
        c[s] = a;
    }
}

// ======== fp16 GEMM, ldmatrix fragments, 3-stage cp.async ========
// rows: 128 x 32 halfs (64B) + 16B pad = 80B/row; stage = 128*80 = 10240B
#define HROWB 80
#define HSTG 10240
#define HSMEM (6*HSTG)      // 61440: A0..A2, B0..B2
#define NIT 16

__global__ __launch_bounds__(256) void gemm_h(
    const __half* __restrict__ A16, const __half* __restrict__ BT16,
    const float* __restrict__ bias, const float* __restrict__ resid,
    float* __restrict__ C, __half* __restrict__ C16,
    const float* __restrict__ rowmu, const float* __restrict__ rowri,
    const float* __restrict__ cs,
    const __half* __restrict__ P16T, const float* __restrict__ cvec,
    const float* __restrict__ scale_p,
    float* __restrict__ ww, float* __restrict__ rw, int nNormal)
{
    extern __shared__ __align__(16) char smraw[];
    float* L = (float*)smraw;          // logits alias [128][68] = 34816B
    __shared__ float csh[128];

    const int tid  = threadIdx.x;
    const int lane = tid & 31;
    const int wid  = tid >> 5;
    const int warp_m = wid >> 2;   // 0..1
    const int warp_n = wid & 3;    // 0..3
    const int gid = lane >> 2;
    const int tig = lane & 3;
    const int m0 = blockIdx.y * 128;
    const bool is_logit = (P16T != nullptr) && ((int)blockIdx.x == nNormal);
    const int n0 = is_logit ? 0 : blockIdx.x * 128;
    const __half* Bsrc = is_logit ? P16T : BT16;

    if (is_logit && tid < 128) csh[tid] = cvec[tid];

    const unsigned sb = (unsigned)__cvta_generic_to_shared(smraw);

    // ldmatrix lane address components
    const int grp = lane >> 3;
    const unsigned aRowL = (unsigned)(warp_m*64 + (grp & 1)*8 + (lane & 7));
    const unsigned aKadd = (unsigned)((grp >> 1) * 16);
    const unsigned bRowL = (unsigned)(warp_n*32 + (grp >> 1)*8 + (lane & 7));
    const unsigned bKadd = (unsigned)((grp & 1) * 16);

    float acc[4][4][4] = {};

    auto stageAB = [&](int st, int k0) {
        #pragma unroll
        for (int h = 0; h < 2; h++) {
            int cch = tid + h*256;
            int r = cch >> 2, j = cch & 3;
            unsigned off = (unsigned)(r*HROWB + j*16);
            cpcg16(sb + st*HSTG + off, A16 + (size_t)(m0 + r)*DIMC + k0 + j*8);
            cpcg16(sb + 3*HSTG + st*HSTG + off, Bsrc + (size_t)(n0 + r)*DIMC + k0 + j*8);
        }
    };

    stageAB(0, 0);  CP_COMMIT();
    stageAB(1, 32); CP_COMMIT();

    for (int it = 0; it < NIT; it++) {
        if (it == NIT - 1) { CP_WAIT0(); } else { CP_WAIT1(); }
        __syncthreads();
        if (it + 2 < NIT) {
            stageAB((it + 2) % 3, (it + 2) * 32);
            CP_COMMIT();
        }
        const int st = it % 3;
        const unsigned aB = sb + st*HSTG + aRowL*HROWB + aKadd;
        const unsigned bB = sb + 3*HSTG + st*HSTG + bRowL*HROWB + bKadd;

        #pragma unroll
        for (int ks = 0; ks < 2; ks++) {
            unsigned af[4][4];
            #pragma unroll
            for (int mt = 0; mt < 4; mt++)
                ldsm_x4(af[mt][0], af[mt][1], af[mt][2], af[mt][3],
                        aB + (unsigned)(mt*16*HROWB + ks*32));
            unsigned bf[4][2];
            #pragma unroll
            for (int ntp = 0; ntp < 2; ntp++)
                ldsm_x4(bf[2*ntp][0], bf[2*ntp][1], bf[2*ntp+1][0], bf[2*ntp+1][1],
                        bB + (unsigned)(ntp*16*HROWB + ks*32));
            #pragma unroll
            for (int mt = 0; mt < 4; mt++)
                #pragma unroll
                for (int nt = 0; nt < 4; nt++)
                    mma_f16(acc[mt][nt], af[mt][0], af[mt][1], af[mt][2], af[mt][3],
                            bf[nt][0], bf[nt][1]);
        }
        __syncthreads();
    }

    if (!is_logit) {
        #pragma unroll
        for (int nt = 0; nt < 4; nt++) {
            int cb = n0 + warp_n * 32 + nt * 8 + 2 * tig;
            float b0 = bias[cb], b1 = bias[cb + 1];
            float cs0 = 0.f, cs1 = 0.f;
            if (rowmu) { cs0 = cs[cb]; cs1 = cs[cb + 1]; }
            #pragma unroll
            for (int mt = 0; mt < 4; mt++) {
                int rA = m0 + warp_m * 64 + mt * 16 + gid;
                int rB = rA + 8;
                size_t offA = (size_t)rA * DIMC + cb;
                size_t offB = (size_t)rB * DIMC + cb;
                if (rowmu) {
                    float muA = rowmu[rA], riA = rowri[rA];
                    float muB = rowmu[rB], riB = rowri[rB];
                    float2 o0, o1;
                    o0.x = riA*acc[mt][nt][0] - riA*muA*cs0 + b0;
                    o0.y = riA*acc[mt][nt][1] - riA*muA*cs1 + b1;
                    o1.x = riB*acc[mt][nt][2] - riB*muB*cs0 + b0;
                    o1.y = riB*acc[mt][nt][3] - riB*muB*cs1 + b1;
                    float2 e0 = *(const float2*)(resid + offA);
                    float2 e1 = *(const float2*)(resid + offB);
                    o0.x += e0.x; o0.y += e0.y;
                    o1.x += e1.x; o1.y += e1.y;
                    *(float2*)(C + offA) = o0;
                    *(float2*)(C + offB) = o1;
                } else {
                    *(__half2*)(C16 + offA) =
                        __floats2half2_rn(acc[mt][nt][0] + b0, acc[mt][nt][1] + b1);
                    *(__half2*)(C16 + offB) =
                        __floats2half2_rn(acc[mt][nt][2] + b0, acc[mt][nt][3] + b1);
                }
            }
        }
    } else {
        const float sc = scale_p[0];
        #pragma unroll
        for (int pass = 0; pass < 2; pass++) {
            if ((warp_n >> 1) == pass) {
                int halfn = warp_n & 1;
                #pragma unroll
                for (int nt = 0; nt < 4; nt++) {
                    int cl = halfn * 32 + nt * 8 + 2 * tig;
                    int cg = pass * 64 + cl;
                    float c0v = csh[cg], c1v = csh[cg + 1];
                    #pragma unroll
                    for (int mt = 0; mt < 4; mt++) {
                        int rr = warp_m * 64 + mt * 16 + gid;
                        L[ rr    *68 + cl    ] = (acc[mt][nt][0] + c0v) * sc;
                        L[ rr    *68 + cl + 1] = (acc[mt][nt][1] + c1v) * sc;
                        L[(rr+8) *68 + cl    ] = (acc[mt][nt][2] + c0v) * sc;
                        L[(rr+8) *68 + cl + 1] = (acc[mt][nt][3] + c1v) * sc;
                    }
                }
            }
            __syncthreads();
            {
                int t = tid >> 1, hh = tid & 1;
                float* Lr = L + t*68 + hh*32;
                float mx = -1e30f;
                #pragma unroll 8
                for (int s = 0; s < 32; s++) mx = fmaxf(mx, Lr[s]);
                mx = fmaxf(mx, __shfl_xor_sync(0xffffffffu, mx, 1));
                float sum = 0.f;
                #pragma unroll 8
                for (int s = 0; s < 32; s++) { float e = expf(Lr[s]-mx); Lr[s] = e; sum += e; }
                sum += __shfl_xor_sync(0xffffffffu, sum, 1);
                float rv = 1.f / sum;
                float* op = (pass ? rw : ww) + (size_t)(m0 + t) * NSLOT + hh*32;
                #pragma unroll
                for (int s = 0; s < 32; s += 4) {
                    float4 w;
                    w.x = Lr[s]*rv; w.y = Lr[s+1]*rv; w.z = Lr[s+2]*rv; w.w = Lr[s+3]*rv;
                    *(float4*)(op + s) = w;
                }
            }
            __syncthreads();
        }
    }
}

// ======== per-chunk tf32 MMA (unchanged proven path) ========
#define CSMEM (64*68*4*2 + 64*132*4)   // 68608

__global__ __launch_bounds__(256) void chunk_attn_mma(
    const float* __restrict__ rw, const float* __restrict__ ww,
    const __half* __restrict__ v16, __half* __restrict__ ret16)
{
    extern __shared__ __align__(16) char cbuf[];
    unsigned* RW = (unsigned*)cbuf;
    unsigned* WT = RW + 64*68;
    unsigned* VS = WT + 64*68;
    const int tid  = threadIdx.x;
    const int lane = tid & 31;
    const int wid  = tid >> 5;
    const int gid = lane >> 2;
    const int tig = lane & 3;
    const int chunk0 = blockIdx.x * CHUNKT;

    #pragma unroll
    for (int k = 0; k < 4; k++) {
        int idx = tid + k*256;
        int r = idx >> 4, c4 = (idx & 15) << 2;
        float4 a = *(const float4*)(rw + (size_t)(chunk0+r)*NSLOT + c4);
        RW[r*68 + c4    ] = f2tf32(a.x);
        RW[r*68 + c4 + 1] = f2tf32(a.y);
        RW[r*68 + c4 + 2] = f2tf32(a.z);
        RW[r*68 + c4 + 3] = f2tf32(a.w);
        float4 b = *(const float4*)(ww + (size_t)(chunk0+r)*NSLOT + c4);
        WT[(c4    )*68 + r] = f2tf32(b.x);
        WT[(c4 + 1)*68 + r] = f2tf32(b.y);
        WT[(c4 + 2)*68 + r] = f2tf32(b.z);
        WT[(c4 + 3)*68 + r] = f2tf32(b.w);
    }
    __syncthreads();

    const int wm = wid >> 2;
    const int wn = wid & 3;
    float a1[2][2][4] = {};
    #pragma unroll
    for (int kk = 0; kk < 64; kk += 8) {
        unsigned af[2][4];
        #pragma unroll
        for (int mt = 0; mt < 2; mt++) {
            int r = wm*32 + mt*16 + gid;
            af[mt][0] = RW[ r     *68 + kk + tig    ];
            af[mt][1] = RW[(r + 8)*68 + kk + tig    ];
            af[mt][2] = RW[ r     *68 + kk + tig + 4];
            af[mt][3] = RW[(r + 8)*68 + kk + tig + 4];
        }
        unsigned bf[2][2];
        #pragma unroll
        for (int nt = 0; nt < 2; nt++) {
            int cc = wn*16 + nt*8 + gid;
            bf[nt][0] = WT[(kk + tig    )*68 + cc];
            bf[nt][1] = WT[(kk + tig + 4)*68 + cc];
        }
        #pragma unroll
        for (int mt = 0; mt < 2; mt++)
            #pragma unroll
            for (int nt = 0; nt < 2; nt++)
                mma_tf32(a1[mt][nt], af[mt][0], af[mt][1], af[mt][2], af[mt][3],
                         bf[nt][0], bf[nt][1]);
    }
    __syncthreads();

    #pragma unroll
    for (int mt = 0; mt < 2; mt++) {
        int r0 = wm*32 + mt*16 + gid;
        #pragma unroll
        for (int nt = 0; nt < 2; nt++) {
            int cc = wn*16 + nt*8 + 2*tig;
            RW[ r0    *68 + cc    ] = f2tf32((cc     <= r0    ) ? a1[mt][nt][0] : 0.f);
            RW[ r0    *68 + cc + 1] = f2tf32((cc + 1 <= r0    ) ? a1[mt][nt][1] : 0.f);
            RW[(r0+8) *68 + cc    ] = f2tf32((cc     <= r0 + 8) ? a1[mt][nt][2] : 0.f);
            RW[(r0+8) *68 + cc + 1] = f2tf32((cc + 1 <= r0 + 8) ? a1[mt][nt][3] : 0.f);
        }
    }
    __syncthreads();

    unsigned afA[8][2][4];
    #pragma unroll
    for (int ks = 0; ks < 8; ks++) {
        #pragma unroll
        for (int mt = 0; mt < 2; mt++) {
            int r = wm*32 + mt*16 + gid;
            afA[ks][mt][0] = RW[ r     *68 + ks*8 + tig    ];
            afA[ks][mt][1] = RW[(r + 8)*68 + ks*8 + tig    ];
            afA[ks][mt][2] = RW[ r     *68 + ks*8 + tig + 4];
            afA[ks][mt][3] = RW[(r + 8)*68 + ks*8 + tig + 4];
        }
    }

    for (int d0 = 0; d0 < DIMC; d0 += 128) {
        #pragma unroll
        for (int k = 0; k < 8; k++) {
            int idx = tid + k*256;
            int r = idx >> 5, c4 = (idx & 31) << 2;
            uint2 hv = *(const uint2*)(v16 + (size_t)(chunk0+r)*DIMC + d0 + c4);
            float2 f0 = __half22float2(*(__half2*)&hv.x);
            float2 f1 = __half22float2(*(__half2*)&hv.y);
            VS[r*132 + c4    ] = f2tf32(f0.x);
            VS[r*132 + c4 + 1] = f2tf32(f0.y);
            VS[r*132 + c4 + 2] = f2tf32(f1.x);
            VS[r*132 + c4 + 3] = f2tf32(f1.y);
        }
        __syncthreads();

        float a2[2][4][4] = {};
        #pragma unroll
        for (int ks = 0; ks < 8; ks++) {
            unsigned bf[4][2];
            #pragma unroll
            for (int nt = 0; nt < 4; nt++) {
                int cc = wn*32 + nt*8 + gid;
                bf[nt][0] = VS[(ks*8 + tig    )*132 + cc];
                bf[nt][1] = VS[(ks*8 + tig + 4)*132 + cc];
            }
            #pragma unroll
            for (int mt = 0; mt < 2; mt++)
                #pragma unroll
                for (int nt = 0; nt < 4; nt++)
                    mma_tf32(a2[mt][nt], afA[ks][mt][0], afA[ks][mt][1],
                             afA[ks][mt][2], afA[ks][mt][3], bf[nt][0], bf[nt][1]);
        }

        #pragma unroll
        for (int mt = 0; mt < 2; mt++) {
            int r0 = wm*32 + mt*16 + gid;
            #pragma unroll
            for (int nt = 0; nt < 4; nt++) {
                int cc = wn*32 + nt*8 + 2*tig;
                *(__half2*)(ret16 + (size_t)(chunk0 + r0    )*DIMC + d0 + cc) =
                    __floats2half2_rn(a2[mt][nt][0], a2[mt][nt][1]);
                *(__half2*)(ret16 + (size_t)(chunk0 + r0 + 8)*DIMC + d0 + cc) =
                    __floats2half2_rn(a2[mt][nt][2], a2[mt][nt][3]);
            }
        }
        __syncthreads();
    }
}

// ======== LN row stats from half ========
__global__ __launch_bounds__(256) void ln_stats(
    const __half* __restrict__ X16, float* __restrict__ mu, float* __restrict__ ri)
{
    const int row = blockIdx.x * 8 + (threadIdx.x >> 5);
    const int lane = threadIdx.x & 31;
    const __half* xr = X16 + (size_t)row * DIMC;
    float s = 0.f, ss = 0.f;
    #pragma unroll
    for (int i = 0; i < 2; i++) {
        uint4 u = *(const uint4*)(xr + lane*8 + i*256);
        const unsigned* up = (const unsigned*)&u;
        #pragma unroll
        for (int j = 0; j < 4; j++) {
            float2 f = __half22float2(*(__half2*)&up[j]);
            s  += f.x + f.y;
            ss += fmaf(f.x, f.x, f.y*f.y);
        }
    }
    #pragma unroll
    for (int o = 16; o > 0; o >>= 1) {
        s  += __shfl_xor_sync(0xffffffffu, s,  o);
        ss += __shfl_xor_sync(0xffffffffu, ss, o);
    }
    if (lane == 0) {
        float m = s * (1.f/512.f);
        mu[row] = m;
        ri[row] = rsqrtf(ss * (1.f/512.f) - m*m + 1e-5f);
    }
}

// ---------------- launch ----------------
extern "C" void kernel_launch(void* const* d_in, const int* in_sizes, int n_in,
                              void* d_out, int out_size)
{
    (void)in_sizes; (void)n_in; (void)out_size;
    const float* x   = (const float*)d_in[0];
    const float* sk  = (const float*)d_in[1];
    const float* Wk  = (const float*)d_in[2];
    const float* bk  = (const float*)d_in[3];
    const float* Wq  = (const float*)d_in[4];
    const float* bq  = (const float*)d_in[5];
    const float* Wv  = (const float*)d_in[6];
    const float* bv  = (const float*)d_in[7];
    const float* sc  = (const float*)d_in[8];
    const float* lng = (const float*)d_in[9];
    const float* lnb = (const float*)d_in[10];
    const float* Wo  = (const float*)d_in[11];
    const float* bo  = (const float*)d_in[12];
    float* out = (float*)d_out;

    float *wwp,*rwp,*cp,*b2p,*csp,*mup,*rip;
    __half *x16p,*v16p,*ret16p,*WvTp,*WoTp,*P16p;
    cudaGetSymbolAddress((void**)&x16p,  g_x16);
    cudaGetSymbolAddress((void**)&v16p,  g_v16);
    cudaGetSymbolAddress((void**)&ret16p,g_ret16);
    cudaGetSymbolAddress((void**)&wwp,   g_ww);
    cudaGetSymbolAddress((void**)&rwp,   g_rw);
    cudaGetSymbolAddress((void**)&cp,    g_c);
    cudaGetSymbolAddress((void**)&b2p,   g_b2);
    cudaGetSymbolAddress((void**)&csp,   g_cs);
    cudaGetSymbolAddress((void**)&mup,   g_mu);
    cudaGetSymbolAddress((void**)&rip,   g_ri);
    cudaGetSymbolAddress((void**)&WvTp,  g_WvT16);
    cudaGetSymbolAddress((void**)&WoTp,  g_WoT16);
    cudaGetSymbolAddress((void**)&P16p,  g_P16T);

    cudaFuncSetAttribute(gemm_h, cudaFuncAttributeMaxDynamicSharedMemorySize, HSMEM);
    cudaFuncSetAttribute(chunk_attn_mma, cudaFuncAttributeMaxDynamicSharedMemorySize, CSMEM);

    prep_kernel<<<DIMC + 2, 128>>>(Wk, bk, Wq, bq, sk, Wv, Wo, lng, lnb, bo,
                                   P16p, cp, WvTp, WoTp, b2p, csp);

    to_half_kernel<<<((size_t)NTOK*DIMC/8)/256, 256>>>(x, x16p);

    dim3 gv(5, NTOK/128);
    gemm_h<<<gv, 256, HSMEM>>>(x16p, WvTp, bv, nullptr, nullptr, v16p,
                               nullptr, nullptr, nullptr,
                               P16p, cp, sc, wwp, rwp, 4);

    chunk_attn_mma<<<NCHUNK, 256, CSMEM>>>(rwp, wwp, v16p, ret16p);

    ln_stats<<<NTOK/8, 256>>>(ret16p, mup, rip);

    dim3 go(4, NTOK/128);
    gemm_h<<<go, 256, HSMEM>>>(ret16p, WoTp, b2p, x, out, nullptr,
                               mup, rip, csp,
                               nullptr, nullptr, nullptr, nullptr, nullptr, 4);
}